// round 1
// baseline (speedup 1.0000x reference)
#include <cuda_runtime.h>

#define CL 4096
#define CS 4096
#define CE 768
#define CH 12
#define CD 64

static __device__ __host__ constexpr float INV_SCALE = 0.036084391824351614f; // 1/sqrt(768)

// Scratch (no cudaMalloc allowed)
__device__ float g_Q[CL * CE];
__device__ float g_K[CS * CE];
__device__ float g_V[CS * CE];
__device__ float g_O[CL * CE];

// ---------------------------------------------------------------------------
// Tiled fp32 GEMM: C[M,N] = A[M,K] @ B[K,N] (+ bias[N] if bias != nullptr)
// 64x64 block tile, BK=32, 256 threads, 4x4 micro-tile per thread.
// ---------------------------------------------------------------------------
__global__ __launch_bounds__(256) void gemm64(const float* __restrict__ A,
                                              const float* __restrict__ B,
                                              const float* __restrict__ bias,
                                              float* __restrict__ C,
                                              int M, int N, int K)
{
    __shared__ float As[64][33];  // [m][k], padded
    __shared__ float Bs[32][65];  // [k][n], padded

    const int tid = threadIdx.x;
    const int tx = tid & 15;      // n direction
    const int ty = tid >> 4;      // m direction
    const int m0 = blockIdx.y * 64;
    const int n0 = blockIdx.x * 64;

    float acc[4][4];
#pragma unroll
    for (int i = 0; i < 4; i++)
#pragma unroll
        for (int j = 0; j < 4; j++) acc[i][j] = 0.f;

    for (int k0 = 0; k0 < K; k0 += 32) {
        // Load A tile 64x32 (512 float4, 2 per thread)
#pragma unroll
        for (int c = 0; c < 2; c++) {
            int lin = tid + c * 256;
            int row = lin >> 3;
            int col = (lin & 7) << 2;
            float4 v = *(const float4*)&A[(size_t)(m0 + row) * K + k0 + col];
            As[row][col + 0] = v.x;
            As[row][col + 1] = v.y;
            As[row][col + 2] = v.z;
            As[row][col + 3] = v.w;
        }
        // Load B tile 32x64
#pragma unroll
        for (int c = 0; c < 2; c++) {
            int lin = tid + c * 256;
            int row = lin >> 4;
            int col = (lin & 15) << 2;
            float4 v = *(const float4*)&B[(size_t)(k0 + row) * N + n0 + col];
            Bs[row][col + 0] = v.x;
            Bs[row][col + 1] = v.y;
            Bs[row][col + 2] = v.z;
            Bs[row][col + 3] = v.w;
        }
        __syncthreads();

#pragma unroll
        for (int kk = 0; kk < 32; kk++) {
            float a[4], b[4];
#pragma unroll
            for (int i = 0; i < 4; i++) a[i] = As[ty * 4 + i][kk];
#pragma unroll
            for (int j = 0; j < 4; j++) b[j] = Bs[kk][tx * 4 + j];
#pragma unroll
            for (int i = 0; i < 4; i++)
#pragma unroll
                for (int j = 0; j < 4; j++) acc[i][j] += a[i] * b[j];
        }
        __syncthreads();
    }

#pragma unroll
    for (int i = 0; i < 4; i++) {
        int m = m0 + ty * 4 + i;
#pragma unroll
        for (int j = 0; j < 4; j++) {
            int n = n0 + tx * 4 + j;
            float v = acc[i][j];
            if (bias) v += bias[n];
            C[(size_t)m * N + n] = v;
        }
    }
}

// ---------------------------------------------------------------------------
// Flash attention: one block per (64-query tile, head).
// Q premultiplied by 1/sqrt(E). Online softmax, register O accumulator.
// Row-group = 16 contiguous lanes -> shfl_xor width 16 reductions.
// ---------------------------------------------------------------------------
__global__ __launch_bounds__(256) void flash_attn(const float* __restrict__ Q,
                                                  const float* __restrict__ K,
                                                  const float* __restrict__ V,
                                                  const int* __restrict__ Msk,
                                                  float* __restrict__ O)
{
    extern __shared__ float sm[];
    float* Qs = sm;              // 64 x 65
    float* Ks = Qs + 64 * 65;    // 64 x 65
    float* Vs = Ks + 64 * 65;    // 64 x 65
    float* Ss = Vs + 64 * 65;    // 64 x 65 : mask bias, then P

    const int h = blockIdx.y;
    const int q0 = blockIdx.x * 64;
    const int tid = threadIdx.x;
    const int tx = tid & 15;     // key / headdim cols
    const int ty = tid >> 4;     // query rows

    // Load Q tile (64 rows x 64 dims), scaled.
#pragma unroll
    for (int c = 0; c < 4; c++) {
        int lin = tid + c * 256;
        int row = lin >> 4;
        int col = (lin & 15) << 2;
        float4 v = *(const float4*)&Q[(size_t)(q0 + row) * CE + h * CD + col];
        float* dst = &Qs[row * 65 + col];
        dst[0] = v.x * INV_SCALE;
        dst[1] = v.y * INV_SCALE;
        dst[2] = v.z * INV_SCALE;
        dst[3] = v.w * INV_SCALE;
    }

    float m_i[4], l_i[4], o[4][4];
#pragma unroll
    for (int i = 0; i < 4; i++) {
        m_i[i] = -1e30f;
        l_i[i] = 0.f;
#pragma unroll
        for (int j = 0; j < 4; j++) o[i][j] = 0.f;
    }

    for (int k0 = 0; k0 < CS; k0 += 64) {
        __syncthreads();  // prior-iter smem reads (and Q load) complete

        // Load K tile, V tile, mask tile (as additive bias into Ss).
#pragma unroll
        for (int c = 0; c < 4; c++) {
            int lin = tid + c * 256;
            int row = lin >> 4;
            int col = (lin & 15) << 2;
            float4 kv = *(const float4*)&K[(size_t)(k0 + row) * CE + h * CD + col];
            float* kd = &Ks[row * 65 + col];
            kd[0] = kv.x; kd[1] = kv.y; kd[2] = kv.z; kd[3] = kv.w;
            float4 vv = *(const float4*)&V[(size_t)(k0 + row) * CE + h * CD + col];
            float* vd = &Vs[row * 65 + col];
            vd[0] = vv.x; vd[1] = vv.y; vd[2] = vv.z; vd[3] = vv.w;
            int4 mv = *(const int4*)&Msk[(size_t)(q0 + row) * CS + k0 + col];
            float* md = &Ss[row * 65 + col];
            md[0] = mv.x ? 0.f : -1e20f;
            md[1] = mv.y ? 0.f : -1e20f;
            md[2] = mv.z ? 0.f : -1e20f;
            md[3] = mv.w ? 0.f : -1e20f;
        }
        __syncthreads();

        // S = Q @ K^T  (4x4 per thread)
        float s[4][4];
#pragma unroll
        for (int i = 0; i < 4; i++)
#pragma unroll
            for (int j = 0; j < 4; j++) s[i][j] = 0.f;

#pragma unroll
        for (int d = 0; d < 64; d++) {
            float a[4], b[4];
#pragma unroll
            for (int i = 0; i < 4; i++) a[i] = Qs[(ty * 4 + i) * 65 + d];
#pragma unroll
            for (int j = 0; j < 4; j++) b[j] = Ks[(tx * 4 + j) * 65 + d];
#pragma unroll
            for (int i = 0; i < 4; i++)
#pragma unroll
                for (int j = 0; j < 4; j++) s[i][j] += a[i] * b[j];
        }

        // Mask bias + online softmax per row.
#pragma unroll
        for (int i = 0; i < 4; i++) {
            const float* mb = &Ss[(ty * 4 + i) * 65 + tx * 4];
            float rmax = -1e30f;
#pragma unroll
            for (int j = 0; j < 4; j++) {
                s[i][j] += mb[j];
                rmax = fmaxf(rmax, s[i][j]);
            }
#pragma unroll
            for (int off = 8; off >= 1; off >>= 1)
                rmax = fmaxf(rmax, __shfl_xor_sync(0xffffffffu, rmax, off, 16));

            float m_new = fmaxf(m_i[i], rmax);
            float corr = __expf(m_i[i] - m_new);
            float rsum = 0.f;
#pragma unroll
            for (int j = 0; j < 4; j++) {
                float p = __expf(s[i][j] - m_new);
                s[i][j] = p;
                rsum += p;
            }
#pragma unroll
            for (int off = 8; off >= 1; off >>= 1)
                rsum += __shfl_xor_sync(0xffffffffu, rsum, off, 16);

            l_i[i] = l_i[i] * corr + rsum;
            m_i[i] = m_new;
#pragma unroll
            for (int j = 0; j < 4; j++) o[i][j] *= corr;
        }

        // Write P to shared (same slots this thread read the bias from).
#pragma unroll
        for (int i = 0; i < 4; i++)
#pragma unroll
            for (int j = 0; j < 4; j++)
                Ss[(ty * 4 + i) * 65 + tx * 4 + j] = s[i][j];
        __syncthreads();

        // O += P @ V
#pragma unroll
        for (int k = 0; k < 64; k++) {
            float a[4], b[4];
#pragma unroll
            for (int i = 0; i < 4; i++) a[i] = Ss[(ty * 4 + i) * 65 + k];
#pragma unroll
            for (int j = 0; j < 4; j++) b[j] = Vs[k * 65 + tx * 4 + j];
#pragma unroll
            for (int i = 0; i < 4; i++)
#pragma unroll
                for (int j = 0; j < 4; j++) o[i][j] += a[i] * b[j];
        }
    }

    // Epilogue: normalize and store.
#pragma unroll
    for (int i = 0; i < 4; i++) {
        float inv = (l_i[i] > 0.f) ? (1.f / l_i[i]) : 0.f;
#pragma unroll
        for (int j = 0; j < 4; j++)
            O[(size_t)(q0 + ty * 4 + i) * CE + h * CD + tx * 4 + j] = o[i][j] * inv;
    }
}

// ---------------------------------------------------------------------------

extern "C" void kernel_launch(void* const* d_in, const int* in_sizes, int n_in,
                              void* d_out, int out_size)
{
    const float* query = (const float*)d_in[0];
    const float* key   = (const float*)d_in[1];
    const float* value = (const float*)d_in[2];
    const int*   mask  = (const int*)d_in[3];
    const float* Wq    = (const float*)d_in[4];
    const float* Wk    = (const float*)d_in[5];
    const float* Wv    = (const float*)d_in[6];
    const float* Wo    = (const float*)d_in[7];
    const float* bo    = (const float*)d_in[8];
    float* out = (float*)d_out;

    float *Qp, *Kp, *Vp, *Op;
    cudaGetSymbolAddress((void**)&Qp, g_Q);
    cudaGetSymbolAddress((void**)&Kp, g_K);
    cudaGetSymbolAddress((void**)&Vp, g_V);
    cudaGetSymbolAddress((void**)&Op, g_O);

    dim3 blk(256);
    dim3 gproj(CE / 64, CL / 64);

    gemm64<<<gproj, blk>>>(query, Wq, nullptr, Qp, CL, CE, CE);
    gemm64<<<gproj, blk>>>(key,   Wk, nullptr, Kp, CS, CE, CE);
    gemm64<<<gproj, blk>>>(value, Wv, nullptr, Vp, CS, CE, CE);

    const int smem_bytes = 4 * 64 * 65 * (int)sizeof(float);  // 66560
    cudaFuncSetAttribute(flash_attn, cudaFuncAttributeMaxDynamicSharedMemorySize,
                         smem_bytes);
    flash_attn<<<dim3(CL / 64, CH), blk, smem_bytes>>>(Qp, Kp, Vp, mask, Op);

    gemm64<<<gproj, blk>>>(Op, Wo, bo, out, CL, CE, CE);
}

// round 2
// speedup vs baseline: 2.6378x; 2.6378x over previous
#include <cuda_runtime.h>
#include <cstdint>

#define CL 4096
#define CS 4096
#define CE 768
#define CH 12
#define CD 64

static __device__ __host__ constexpr float INV_SCALE = 0.036084391824351614f; // 1/sqrt(768)

// Scratch (no cudaMalloc allowed)
__device__ float g_Q[CL * CE];
__device__ float g_K[CS * CE];
__device__ float g_V[CS * CE];
__device__ float g_O[CL * CE];

// ---------------------------------------------------------------------------
// helpers
// ---------------------------------------------------------------------------
__device__ __forceinline__ float to_tf32(float x) {
    uint32_t u;
    asm("cvt.rna.tf32.f32 %0, %1;" : "=r"(u) : "f"(x));
    return __uint_as_float(u);
}

__device__ __forceinline__ void mma_tf32(float c[4], uint32_t a0, uint32_t a1,
                                         uint32_t a2, uint32_t a3,
                                         uint32_t b0, uint32_t b1) {
    asm volatile(
        "mma.sync.aligned.m16n8k8.row.col.f32.tf32.tf32.f32 "
        "{%0,%1,%2,%3}, {%4,%5,%6,%7}, {%8,%9}, {%0,%1,%2,%3};\n"
        : "+f"(c[0]), "+f"(c[1]), "+f"(c[2]), "+f"(c[3])
        : "r"(a0), "r"(a1), "r"(a2), "r"(a3), "r"(b0), "r"(b1));
}

// ---------------------------------------------------------------------------
// tf32 GEMM: C[M,N] = A[M,K] @ W[K,N] (+bias). Tile 128x64, 256 thr (8 warps),
// each warp computes 16 rows x 64 cols. K step 32.
// ---------------------------------------------------------------------------
__global__ __launch_bounds__(256) void gemm_tc(const float* __restrict__ A,
                                               const float* __restrict__ W,
                                               const float* __restrict__ bias,
                                               float* __restrict__ C,
                                               int M, int N, int K)
{
    __shared__ float As[128 * 36];  // [row][k], stride 36 -> conflict-free a-frags
    __shared__ float Bt[64 * 36];   // [n][k],  stride 36 -> conflict-free b-frags

    const int tid = threadIdx.x;
    const int wid = tid >> 5;
    const int ln  = tid & 31;
    const int gid = ln >> 2;   // 0..7
    const int tig = ln & 3;    // 0..3
    const int m0 = blockIdx.y * 128;
    const int n0 = blockIdx.x * 64;
    const int qb = wid * 16;

    float c[8][4];
#pragma unroll
    for (int nf = 0; nf < 8; nf++)
#pragma unroll
        for (int j = 0; j < 4; j++) c[nf][j] = 0.f;

    for (int k0 = 0; k0 < K; k0 += 32) {
        // A tile 128x32 : 1024 float4, 4 per thread
#pragma unroll
        for (int i = 0; i < 4; i++) {
            int lin = tid + i * 256;
            int row = lin >> 3;
            int col = (lin & 7) << 2;
            float4 v = *(const float4*)&A[(size_t)(m0 + row) * K + k0 + col];
            float* d = &As[row * 36 + col];
            d[0] = to_tf32(v.x); d[1] = to_tf32(v.y);
            d[2] = to_tf32(v.z); d[3] = to_tf32(v.w);
        }
        // W tile 32x64, stored transposed Bt[n][k] : 512 float4, 2 per thread
#pragma unroll
        for (int i = 0; i < 2; i++) {
            int lin = tid + i * 256;
            int kr = lin >> 4;
            int nc = (lin & 15) << 2;
            float4 v = *(const float4*)&W[(size_t)(k0 + kr) * N + n0 + nc];
            Bt[(nc + 0) * 36 + kr] = to_tf32(v.x);
            Bt[(nc + 1) * 36 + kr] = to_tf32(v.y);
            Bt[(nc + 2) * 36 + kr] = to_tf32(v.z);
            Bt[(nc + 3) * 36 + kr] = to_tf32(v.w);
        }
        __syncthreads();

#pragma unroll
        for (int kk = 0; kk < 4; kk++) {
            const int d0 = kk * 8;
            uint32_t a0 = __float_as_uint(As[(qb + gid) * 36 + d0 + tig]);
            uint32_t a1 = __float_as_uint(As[(qb + gid + 8) * 36 + d0 + tig]);
            uint32_t a2 = __float_as_uint(As[(qb + gid) * 36 + d0 + tig + 4]);
            uint32_t a3 = __float_as_uint(As[(qb + gid + 8) * 36 + d0 + tig + 4]);
#pragma unroll
            for (int nf = 0; nf < 8; nf++) {
                uint32_t b0 = __float_as_uint(Bt[(nf * 8 + gid) * 36 + d0 + tig]);
                uint32_t b1 = __float_as_uint(Bt[(nf * 8 + gid) * 36 + d0 + tig + 4]);
                mma_tf32(c[nf], a0, a1, a2, a3, b0, b1);
            }
        }
        __syncthreads();
    }

    const int r0 = m0 + qb + gid;
    const int r1 = r0 + 8;
#pragma unroll
    for (int nf = 0; nf < 8; nf++) {
        int n = n0 + nf * 8 + 2 * tig;
        float b0v = bias ? bias[n] : 0.f;
        float b1v = bias ? bias[n + 1] : 0.f;
        C[(size_t)r0 * N + n]     = c[nf][0] + b0v;
        C[(size_t)r0 * N + n + 1] = c[nf][1] + b1v;
        C[(size_t)r1 * N + n]     = c[nf][2] + b0v;
        C[(size_t)r1 * N + n + 1] = c[nf][3] + b1v;
    }
}

// ---------------------------------------------------------------------------
// Flash attention on tensor cores. Block = (128-query tile, head).
// 8 warps; warp w owns query rows [w*16, w*16+16) for the WHOLE pipeline:
// S mma -> warp-local online softmax -> P staged in smem -> PV mma.
// ---------------------------------------------------------------------------
__global__ __launch_bounds__(256) void flash_tc(const float* __restrict__ Qg,
                                                const float* __restrict__ Kg,
                                                const float* __restrict__ Vg,
                                                const int* __restrict__ Msk,
                                                float* __restrict__ Og)
{
    extern __shared__ float sm[];
    float* Qs = sm;                   // 128 x 64, stride 68 (tf32)
    float* Ks = Qs + 128 * 68;        // 64 x 64, stride 68 (tf32)  [key][d]
    float* Vt = Ks + 64 * 68;         // 64 x 64, stride 68 (tf32)  [dim][key]
    float* Bs = Vt + 64 * 68;         // 128 x 64, stride 68: mask bias, then P

    const int h  = blockIdx.y;
    const int q0 = blockIdx.x * 128;
    const int tid = threadIdx.x;
    const int wid = tid >> 5;
    const int ln  = tid & 31;
    const int gid = ln >> 2;
    const int tig = ln & 3;
    const int qb = wid * 16;
    const int r0 = qb + gid;
    const int r1 = r0 + 8;

    // Load Q tile (scaled, tf32): 128x64 = 2048 float4, 8 per thread
#pragma unroll
    for (int i = 0; i < 8; i++) {
        int lin = tid + i * 256;
        int row = lin >> 4;
        int col = (lin & 15) << 2;
        float4 v = *(const float4*)&Qg[(size_t)(q0 + row) * CE + h * CD + col];
        float* d = &Qs[row * 68 + col];
        d[0] = to_tf32(v.x * INV_SCALE);
        d[1] = to_tf32(v.y * INV_SCALE);
        d[2] = to_tf32(v.z * INV_SCALE);
        d[3] = to_tf32(v.w * INV_SCALE);
    }

    float m_i[2] = {-1e30f, -1e30f};
    float l_i[2] = {0.f, 0.f};
    float o[8][4];
#pragma unroll
    for (int nf = 0; nf < 8; nf++)
#pragma unroll
        for (int j = 0; j < 4; j++) o[nf][j] = 0.f;

    for (int k0 = 0; k0 < CS; k0 += 64) {
        __syncthreads();  // prior-iter smem reads done

        // K tile + V tile (V transposed): 1024 float4 each, 4/thread
#pragma unroll
        for (int i = 0; i < 4; i++) {
            int lin = tid + i * 256;
            int row = lin >> 4;
            int col = (lin & 15) << 2;
            float4 kv = *(const float4*)&Kg[(size_t)(k0 + row) * CE + h * CD + col];
            float* kd = &Ks[row * 68 + col];
            kd[0] = to_tf32(kv.x); kd[1] = to_tf32(kv.y);
            kd[2] = to_tf32(kv.z); kd[3] = to_tf32(kv.w);
            float4 vv = *(const float4*)&Vg[(size_t)(k0 + row) * CE + h * CD + col];
            Vt[(col + 0) * 68 + row] = to_tf32(vv.x);
            Vt[(col + 1) * 68 + row] = to_tf32(vv.y);
            Vt[(col + 2) * 68 + row] = to_tf32(vv.z);
            Vt[(col + 3) * 68 + row] = to_tf32(vv.w);
        }
        // mask -> additive bias: 128x64 ints, 8 int4/thread
#pragma unroll
        for (int i = 0; i < 8; i++) {
            int lin = tid + i * 256;
            int row = lin >> 4;
            int col = (lin & 15) << 2;
            int4 mv = *(const int4*)&Msk[(size_t)(q0 + row) * CS + k0 + col];
            float* md = &Bs[row * 68 + col];
            md[0] = mv.x ? 0.f : -1e20f;
            md[1] = mv.y ? 0.f : -1e20f;
            md[2] = mv.z ? 0.f : -1e20f;
            md[3] = mv.w ? 0.f : -1e20f;
        }
        __syncthreads();

        // S = Q @ K^T  (warp: 16 x 64)
        float s[8][4];
#pragma unroll
        for (int nf = 0; nf < 8; nf++)
#pragma unroll
            for (int j = 0; j < 4; j++) s[nf][j] = 0.f;

#pragma unroll
        for (int kk = 0; kk < 8; kk++) {
            const int d0 = kk * 8;
            uint32_t a0 = __float_as_uint(Qs[(qb + gid) * 68 + d0 + tig]);
            uint32_t a1 = __float_as_uint(Qs[(qb + gid + 8) * 68 + d0 + tig]);
            uint32_t a2 = __float_as_uint(Qs[(qb + gid) * 68 + d0 + tig + 4]);
            uint32_t a3 = __float_as_uint(Qs[(qb + gid + 8) * 68 + d0 + tig + 4]);
#pragma unroll
            for (int nf = 0; nf < 8; nf++) {
                uint32_t b0 = __float_as_uint(Ks[(nf * 8 + gid) * 68 + d0 + tig]);
                uint32_t b1 = __float_as_uint(Ks[(nf * 8 + gid) * 68 + d0 + tig + 4]);
                mma_tf32(s[nf], a0, a1, a2, a3, b0, b1);
            }
        }

        // add mask bias
#pragma unroll
        for (int nf = 0; nf < 8; nf++) {
            int cc = nf * 8 + 2 * tig;
            s[nf][0] += Bs[r0 * 68 + cc];
            s[nf][1] += Bs[r0 * 68 + cc + 1];
            s[nf][2] += Bs[r1 * 68 + cc];
            s[nf][3] += Bs[r1 * 68 + cc + 1];
        }

        // online softmax (rows r0, r1; 4 lanes per row)
        float mx0 = -1e30f, mx1 = -1e30f;
#pragma unroll
        for (int nf = 0; nf < 8; nf++) {
            mx0 = fmaxf(mx0, fmaxf(s[nf][0], s[nf][1]));
            mx1 = fmaxf(mx1, fmaxf(s[nf][2], s[nf][3]));
        }
#pragma unroll
        for (int off = 1; off <= 2; off <<= 1) {
            mx0 = fmaxf(mx0, __shfl_xor_sync(0xffffffffu, mx0, off));
            mx1 = fmaxf(mx1, __shfl_xor_sync(0xffffffffu, mx1, off));
        }
        float mn0 = fmaxf(m_i[0], mx0);
        float mn1 = fmaxf(m_i[1], mx1);
        float cr0 = __expf(m_i[0] - mn0);
        float cr1 = __expf(m_i[1] - mn1);

        float sum0 = 0.f, sum1 = 0.f;
#pragma unroll
        for (int nf = 0; nf < 8; nf++) {
            s[nf][0] = __expf(s[nf][0] - mn0);
            s[nf][1] = __expf(s[nf][1] - mn0);
            s[nf][2] = __expf(s[nf][2] - mn1);
            s[nf][3] = __expf(s[nf][3] - mn1);
            sum0 += s[nf][0] + s[nf][1];
            sum1 += s[nf][2] + s[nf][3];
        }
#pragma unroll
        for (int off = 1; off <= 2; off <<= 1) {
            sum0 += __shfl_xor_sync(0xffffffffu, sum0, off);
            sum1 += __shfl_xor_sync(0xffffffffu, sum1, off);
        }
        l_i[0] = l_i[0] * cr0 + sum0;
        l_i[1] = l_i[1] * cr1 + sum1;
        m_i[0] = mn0;
        m_i[1] = mn1;
#pragma unroll
        for (int nf = 0; nf < 8; nf++) {
            o[nf][0] *= cr0; o[nf][1] *= cr0;
            o[nf][2] *= cr1; o[nf][3] *= cr1;
        }

        // stage P (tf32) into Bs (warp-private rows; bias already consumed)
#pragma unroll
        for (int nf = 0; nf < 8; nf++) {
            int cc = nf * 8 + 2 * tig;
            Bs[r0 * 68 + cc]     = to_tf32(s[nf][0]);
            Bs[r0 * 68 + cc + 1] = to_tf32(s[nf][1]);
            Bs[r1 * 68 + cc]     = to_tf32(s[nf][2]);
            Bs[r1 * 68 + cc + 1] = to_tf32(s[nf][3]);
        }
        __syncwarp();

        // O += P @ V   (warp: 16 x 64, K = 64 keys)
#pragma unroll
        for (int kk = 0; kk < 8; kk++) {
            const int kb = kk * 8;
            uint32_t a0 = __float_as_uint(Bs[r0 * 68 + kb + tig]);
            uint32_t a1 = __float_as_uint(Bs[r1 * 68 + kb + tig]);
            uint32_t a2 = __float_as_uint(Bs[r0 * 68 + kb + tig + 4]);
            uint32_t a3 = __float_as_uint(Bs[r1 * 68 + kb + tig + 4]);
#pragma unroll
            for (int nf = 0; nf < 8; nf++) {
                uint32_t b0 = __float_as_uint(Vt[(nf * 8 + gid) * 68 + kb + tig]);
                uint32_t b1 = __float_as_uint(Vt[(nf * 8 + gid) * 68 + kb + tig + 4]);
                mma_tf32(o[nf], a0, a1, a2, a3, b0, b1);
            }
        }
    }

    // epilogue
    float inv0 = (l_i[0] > 0.f) ? (1.f / l_i[0]) : 0.f;
    float inv1 = (l_i[1] > 0.f) ? (1.f / l_i[1]) : 0.f;
#pragma unroll
    for (int nf = 0; nf < 8; nf++) {
        int cc = h * CD + nf * 8 + 2 * tig;
        Og[(size_t)(q0 + r0) * CE + cc]     = o[nf][0] * inv0;
        Og[(size_t)(q0 + r0) * CE + cc + 1] = o[nf][1] * inv0;
        Og[(size_t)(q0 + r1) * CE + cc]     = o[nf][2] * inv1;
        Og[(size_t)(q0 + r1) * CE + cc + 1] = o[nf][3] * inv1;
    }
}

// ---------------------------------------------------------------------------

extern "C" void kernel_launch(void* const* d_in, const int* in_sizes, int n_in,
                              void* d_out, int out_size)
{
    const float* query = (const float*)d_in[0];
    const float* key   = (const float*)d_in[1];
    const float* value = (const float*)d_in[2];
    const int*   mask  = (const int*)d_in[3];
    const float* Wq    = (const float*)d_in[4];
    const float* Wk    = (const float*)d_in[5];
    const float* Wv    = (const float*)d_in[6];
    const float* Wo    = (const float*)d_in[7];
    const float* bo    = (const float*)d_in[8];
    float* out = (float*)d_out;

    float *Qp, *Kp, *Vp, *Op;
    cudaGetSymbolAddress((void**)&Qp, g_Q);
    cudaGetSymbolAddress((void**)&Kp, g_K);
    cudaGetSymbolAddress((void**)&Vp, g_V);
    cudaGetSymbolAddress((void**)&Op, g_O);

    dim3 blk(256);
    dim3 gproj(CE / 64, CL / 128);

    gemm_tc<<<gproj, blk>>>(query, Wq, nullptr, Qp, CL, CE, CE);
    gemm_tc<<<gproj, blk>>>(key,   Wk, nullptr, Kp, CS, CE, CE);
    gemm_tc<<<gproj, blk>>>(value, Wv, nullptr, Vp, CS, CE, CE);

    const int smem_bytes = (128 + 64 + 64 + 128) * 68 * (int)sizeof(float); // 104448
    cudaFuncSetAttribute(flash_tc, cudaFuncAttributeMaxDynamicSharedMemorySize,
                         smem_bytes);
    flash_tc<<<dim3(CL / 128, CH), blk, smem_bytes>>>(Qp, Kp, Vp, mask, Op);

    gemm_tc<<<gproj, blk>>>(Op, Wo, bo, out, CL, CE, CE);
}

// round 3
// speedup vs baseline: 2.7339x; 1.0364x over previous
#include <cuda_runtime.h>
#include <cstdint>

#define CL 4096
#define CS 4096
#define CE 768
#define CH 12
#define CD 64
#define FSTR 72
#define GSTR 40

static __device__ __host__ constexpr float INV_SCALE = 0.036084391824351614f; // 1/sqrt(768)

// Scratch (no cudaMalloc allowed)
__device__ float g_Q[CL * CE];
__device__ float g_K[CS * CE];
__device__ float g_V[CS * CE];
__device__ float g_O[CL * CE];
__device__ uint32_t g_MB[(size_t)CL * CS / 32];

// ---------------------------------------------------------------------------
__device__ __forceinline__ float to_tf32(float x) {
    uint32_t u;
    asm("cvt.rna.tf32.f32 %0, %1;" : "=r"(u) : "f"(x));
    return __uint_as_float(u);
}

__device__ __forceinline__ void mma_tf32(float c[4], float a0, float a1,
                                         float a2, float a3, float b0, float b1) {
    asm volatile(
        "mma.sync.aligned.m16n8k8.row.col.f32.tf32.tf32.f32 "
        "{%0,%1,%2,%3}, {%4,%5,%6,%7}, {%8,%9}, {%0,%1,%2,%3};\n"
        : "+f"(c[0]), "+f"(c[1]), "+f"(c[2]), "+f"(c[3])
        : "r"(__float_as_uint(a0)), "r"(__float_as_uint(a1)),
          "r"(__float_as_uint(a2)), "r"(__float_as_uint(a3)),
          "r"(__float_as_uint(b0)), "r"(__float_as_uint(b1)));
}

// ---------------------------------------------------------------------------
// Pack mask to bits: bit i of word w = mask[w*32+i] != 0
// ---------------------------------------------------------------------------
__global__ __launch_bounds__(256) void pack_mask(const int* __restrict__ m,
                                                 uint32_t* __restrict__ mb) {
    int idx = blockIdx.x * 256 + threadIdx.x;
    uint32_t b = __ballot_sync(0xffffffffu, m[idx] != 0);
    if ((threadIdx.x & 31) == 0) mb[idx >> 5] = b;
}

// ---------------------------------------------------------------------------
// tf32 GEMM: C = A[M,K] @ W[K,N] (+bias). Tile 128x64, 128 thr (4 warps),
// warp tile 32x64. Permuted-k smem layout, all fragment loads LDS.64.
// ---------------------------------------------------------------------------
__global__ __launch_bounds__(128) void gemm_tc(const float* __restrict__ A,
                                               const float* __restrict__ W,
                                               const float* __restrict__ bias,
                                               float* __restrict__ C,
                                               int M, int N, int K)
{
    __shared__ float As[128 * GSTR];
    __shared__ float Bt[64 * GSTR];

    const int tid = threadIdx.x;
    const int wid = tid >> 5;
    const int ln  = tid & 31;
    const int gid = ln >> 2;
    const int tig = ln & 3;
    const int qb  = wid * 32;
    const int m0 = blockIdx.y * 128;
    const int n0 = blockIdx.x * 64;

    float c[2][8][4];
#pragma unroll
    for (int m = 0; m < 2; m++)
#pragma unroll
        for (int nf = 0; nf < 8; nf++)
#pragma unroll
            for (int j = 0; j < 4; j++) c[m][nf][j] = 0.f;

    for (int k0 = 0; k0 < K; k0 += 32) {
        // A tile 128x32 (perm layout)
#pragma unroll
        for (int i = 0; i < 8; i++) {
            int lin = tid + i * 128;
            int row = lin >> 3;
            int col = (lin & 7) << 2;
            float4 v = *(const float4*)&A[(size_t)(m0 + row) * K + k0 + col];
            float* d = &As[row * GSTR + ((col >> 3) << 3) + ((col >> 2) & 1)];
            d[0] = to_tf32(v.x); d[2] = to_tf32(v.y);
            d[4] = to_tf32(v.z); d[6] = to_tf32(v.w);
        }
        // W tile 32x64 -> Bt[n][k] with perm + group swizzle
#pragma unroll
        for (int i = 0; i < 4; i++) {
            int lin = tid + i * 128;
            int kr = lin >> 4;
            int nc = (lin & 15) << 2;
            float4 v = *(const float4*)&W[(size_t)(k0 + kr) * N + n0 + nc];
            int grp = (kr >> 3) ^ ((nc >> 3) & 3);
            int off = (grp << 3) + 2 * (kr & 3) + ((kr >> 2) & 1);
            Bt[(nc + 0) * GSTR + off] = to_tf32(v.x);
            Bt[(nc + 1) * GSTR + off] = to_tf32(v.y);
            Bt[(nc + 2) * GSTR + off] = to_tf32(v.z);
            Bt[(nc + 3) * GSTR + off] = to_tf32(v.w);
        }
        __syncthreads();

#pragma unroll
        for (int kk = 0; kk < 4; kk++) {
            float2 aL[2], aH[2];
#pragma unroll
            for (int m = 0; m < 2; m++) {
                aL[m] = *(const float2*)&As[(qb + m * 16 + gid) * GSTR + kk * 8 + 2 * tig];
                aH[m] = *(const float2*)&As[(qb + m * 16 + gid + 8) * GSTR + kk * 8 + 2 * tig];
            }
#pragma unroll
            for (int nf = 0; nf < 8; nf++) {
                int grp = kk ^ (nf & 3);
                float2 bb = *(const float2*)&Bt[(nf * 8 + gid) * GSTR + (grp << 3) + 2 * tig];
#pragma unroll
                for (int m = 0; m < 2; m++)
                    mma_tf32(c[m][nf], aL[m].x, aH[m].x, aL[m].y, aH[m].y, bb.x, bb.y);
            }
        }
        __syncthreads();
    }

#pragma unroll
    for (int m = 0; m < 2; m++) {
        int r0 = m0 + qb + m * 16 + gid;
        int r1 = r0 + 8;
#pragma unroll
        for (int nf = 0; nf < 8; nf++) {
            int n = n0 + nf * 8 + 2 * tig;
            float b0v = bias ? bias[n] : 0.f;
            float b1v = bias ? bias[n + 1] : 0.f;
            float2 v0 = make_float2(c[m][nf][0] + b0v, c[m][nf][1] + b1v);
            float2 v1 = make_float2(c[m][nf][2] + b0v, c[m][nf][3] + b1v);
            *(float2*)&C[(size_t)r0 * N + n] = v0;
            *(float2*)&C[(size_t)r1 * N + n] = v1;
        }
    }
}

// ---------------------------------------------------------------------------
// Flash attention, tensor cores. Block = (128-query tile, head), 4 warps,
// warp owns 32 query rows. Permuted-k smem, vectorized fragment loads,
// bitmask applied in registers.
// ---------------------------------------------------------------------------
__global__ __launch_bounds__(128) void flash_tc(const float* __restrict__ Qg,
                                                const float* __restrict__ Kg,
                                                const float* __restrict__ Vg,
                                                const uint32_t* __restrict__ MBg,
                                                float* __restrict__ Og)
{
    extern __shared__ float smx[];
    float* Qs = smx;                 // 128 x FSTR
    float* Ks = Qs + 128 * FSTR;     // 64 x FSTR
    float* Vt = Ks + 64 * FSTR;      // 64 x FSTR (d-major, key perm + XOR grp)
    float* Ps = Vt + 64 * FSTR;      // 128 x FSTR

    const uint2* MB2 = (const uint2*)MBg;

    const int h  = blockIdx.y;
    const int q0 = blockIdx.x * 128;
    const int tid = threadIdx.x;
    const int wid = tid >> 5;
    const int ln  = tid & 31;
    const int gid = ln >> 2;
    const int tig = ln & 3;
    const int qb = wid * 32;
    const int pc0 = 2 * ((2 * tig) & 3) + (tig >> 1);  // perm(2*tig); pc1 = pc0+2

    // Q fill (scaled, tf32, perm layout)
#pragma unroll
    for (int i = 0; i < 16; i++) {
        int lin = tid + i * 128;
        int row = lin >> 4;
        int col = (lin & 15) << 2;
        float4 v = *(const float4*)&Qg[(size_t)(q0 + row) * CE + h * CD + col];
        float* d = &Qs[row * FSTR + ((col >> 3) << 3) + ((col >> 2) & 1)];
        d[0] = to_tf32(v.x * INV_SCALE);
        d[2] = to_tf32(v.y * INV_SCALE);
        d[4] = to_tf32(v.z * INV_SCALE);
        d[6] = to_tf32(v.w * INV_SCALE);
    }

    float m_i[4] = {-1e30f, -1e30f, -1e30f, -1e30f};
    float l_i[4] = {0.f, 0.f, 0.f, 0.f};
    float o[2][8][4];
#pragma unroll
    for (int m = 0; m < 2; m++)
#pragma unroll
        for (int nf = 0; nf < 8; nf++)
#pragma unroll
            for (int j = 0; j < 4; j++) o[m][nf][j] = 0.f;

    const int mrow = q0 + qb + gid;

    for (int k0 = 0; k0 < CS; k0 += 64) {
        __syncthreads();  // prior-iter Ks/Vt reads done

        // K tile + Vt (transposed, perm + XOR-group swizzle)
#pragma unroll
        for (int i = 0; i < 8; i++) {
            int lin = tid + i * 128;
            int row = lin >> 4;
            int col = (lin & 15) << 2;
            float4 kv = *(const float4*)&Kg[(size_t)(k0 + row) * CE + h * CD + col];
            float* kd = &Ks[row * FSTR + ((col >> 3) << 3) + ((col >> 2) & 1)];
            kd[0] = to_tf32(kv.x); kd[2] = to_tf32(kv.y);
            kd[4] = to_tf32(kv.z); kd[6] = to_tf32(kv.w);
            float4 vv = *(const float4*)&Vg[(size_t)(k0 + row) * CE + h * CD + col];
            int kgrp = row >> 3;
            int koff = 2 * (row & 3) + ((row >> 2) & 1);
            int dg = col >> 3;
            int goff = ((kgrp ^ dg) << 3) + koff;
            Vt[(col + 0) * FSTR + goff] = to_tf32(vv.x);
            Vt[(col + 1) * FSTR + goff] = to_tf32(vv.y);
            Vt[(col + 2) * FSTR + goff] = to_tf32(vv.z);
            Vt[(col + 3) * FSTR + goff] = to_tf32(vv.w);
        }

        // mask bits for this tile (4 rows per thread)
        uint2 mw[2][2];
#pragma unroll
        for (int m = 0; m < 2; m++) {
            mw[m][0] = MB2[(size_t)(mrow + m * 16) * 64 + (k0 >> 6)];
            mw[m][1] = MB2[(size_t)(mrow + m * 16 + 8) * 64 + (k0 >> 6)];
        }
        __syncthreads();

        // S = Q @ K^T  (warp: 32 x 64)
        float s[2][8][4];
#pragma unroll
        for (int m = 0; m < 2; m++)
#pragma unroll
            for (int nf = 0; nf < 8; nf++)
#pragma unroll
                for (int j = 0; j < 4; j++) s[m][nf][j] = 0.f;

#pragma unroll
        for (int kk = 0; kk < 8; kk++) {
            float2 aL[2], aH[2];
#pragma unroll
            for (int m = 0; m < 2; m++) {
                aL[m] = *(const float2*)&Qs[(qb + m * 16 + gid) * FSTR + kk * 8 + 2 * tig];
                aH[m] = *(const float2*)&Qs[(qb + m * 16 + gid + 8) * FSTR + kk * 8 + 2 * tig];
            }
#pragma unroll
            for (int nf = 0; nf < 8; nf++) {
                float2 bb = *(const float2*)&Ks[(nf * 8 + gid) * FSTR + kk * 8 + 2 * tig];
#pragma unroll
                for (int m = 0; m < 2; m++)
                    mma_tf32(s[m][nf], aL[m].x, aH[m].x, aL[m].y, aH[m].y, bb.x, bb.y);
            }
        }

        // online softmax + mask + stage P
#pragma unroll
        for (int m = 0; m < 2; m++) {
            float mx0 = -1e30f, mx1 = -1e30f;
#pragma unroll
            for (int nf = 0; nf < 8; nf++) {
                mx0 = fmaxf(mx0, fmaxf(s[m][nf][0], s[m][nf][1]));
                mx1 = fmaxf(mx1, fmaxf(s[m][nf][2], s[m][nf][3]));
            }
#pragma unroll
            for (int off = 1; off <= 2; off <<= 1) {
                mx0 = fmaxf(mx0, __shfl_xor_sync(0xffffffffu, mx0, off));
                mx1 = fmaxf(mx1, __shfl_xor_sync(0xffffffffu, mx1, off));
            }
            float mn0 = fmaxf(m_i[2 * m], mx0);
            float mn1 = fmaxf(m_i[2 * m + 1], mx1);
            float cr0 = __expf(m_i[2 * m] - mn0);
            float cr1 = __expf(m_i[2 * m + 1] - mn1);

            float sum0 = 0.f, sum1 = 0.f;
#pragma unroll
            for (int nf = 0; nf < 8; nf++) {
                uint32_t w0 = (nf < 4) ? mw[m][0].x : mw[m][0].y;
                uint32_t w1 = (nf < 4) ? mw[m][1].x : mw[m][1].y;
                int sh = ((nf & 3) << 3) + 2 * tig;
                float p0 = __expf(s[m][nf][0] - mn0);
                float p1 = __expf(s[m][nf][1] - mn0);
                float p2 = __expf(s[m][nf][2] - mn1);
                float p3 = __expf(s[m][nf][3] - mn1);
                p0 = ((w0 >> sh) & 1) ? p0 : 0.f;
                p1 = ((w0 >> (sh + 1)) & 1) ? p1 : 0.f;
                p2 = ((w1 >> sh) & 1) ? p2 : 0.f;
                p3 = ((w1 >> (sh + 1)) & 1) ? p3 : 0.f;
                s[m][nf][0] = p0; s[m][nf][1] = p1;
                s[m][nf][2] = p2; s[m][nf][3] = p3;
                sum0 += p0 + p1;
                sum1 += p2 + p3;
            }
#pragma unroll
            for (int off = 1; off <= 2; off <<= 1) {
                sum0 += __shfl_xor_sync(0xffffffffu, sum0, off);
                sum1 += __shfl_xor_sync(0xffffffffu, sum1, off);
            }
            l_i[2 * m]     = l_i[2 * m] * cr0 + sum0;
            l_i[2 * m + 1] = l_i[2 * m + 1] * cr1 + sum1;
            m_i[2 * m] = mn0;
            m_i[2 * m + 1] = mn1;
#pragma unroll
            for (int nf = 0; nf < 8; nf++) {
                o[m][nf][0] *= cr0; o[m][nf][1] *= cr0;
                o[m][nf][2] *= cr1; o[m][nf][3] *= cr1;
            }
            // stage P (perm scatter; warp-private rows)
#pragma unroll
            for (int nf = 0; nf < 8; nf++) {
                float* pr0 = &Ps[(qb + m * 16 + gid) * FSTR + nf * 8];
                float* pr1 = &Ps[(qb + m * 16 + gid + 8) * FSTR + nf * 8];
                pr0[pc0]     = s[m][nf][0];
                pr0[pc0 + 2] = s[m][nf][1];
                pr1[pc0]     = s[m][nf][2];
                pr1[pc0 + 2] = s[m][nf][3];
            }
        }
        __syncwarp();

        // O += P @ V
#pragma unroll
        for (int kk = 0; kk < 8; kk++) {
            float2 aL[2], aH[2];
#pragma unroll
            for (int m = 0; m < 2; m++) {
                aL[m] = *(const float2*)&Ps[(qb + m * 16 + gid) * FSTR + kk * 8 + 2 * tig];
                aH[m] = *(const float2*)&Ps[(qb + m * 16 + gid + 8) * FSTR + kk * 8 + 2 * tig];
            }
#pragma unroll
            for (int nf = 0; nf < 8; nf++) {
                float2 vb = *(const float2*)&Vt[(nf * 8 + gid) * FSTR + ((kk ^ nf) << 3) + 2 * tig];
#pragma unroll
                for (int m = 0; m < 2; m++)
                    mma_tf32(o[m][nf], aL[m].x, aH[m].x, aL[m].y, aH[m].y, vb.x, vb.y);
            }
        }
    }

    // epilogue
#pragma unroll
    for (int m = 0; m < 2; m++) {
        float inv0 = (l_i[2 * m] > 0.f) ? (1.f / l_i[2 * m]) : 0.f;
        float inv1 = (l_i[2 * m + 1] > 0.f) ? (1.f / l_i[2 * m + 1]) : 0.f;
        int r0 = q0 + qb + m * 16 + gid;
#pragma unroll
        for (int nf = 0; nf < 8; nf++) {
            int cc = h * CD + nf * 8 + 2 * tig;
            *(float2*)&Og[(size_t)r0 * CE + cc] =
                make_float2(o[m][nf][0] * inv0, o[m][nf][1] * inv0);
            *(float2*)&Og[(size_t)(r0 + 8) * CE + cc] =
                make_float2(o[m][nf][2] * inv1, o[m][nf][3] * inv1);
        }
    }
}

// ---------------------------------------------------------------------------

extern "C" void kernel_launch(void* const* d_in, const int* in_sizes, int n_in,
                              void* d_out, int out_size)
{
    const float* query = (const float*)d_in[0];
    const float* key   = (const float*)d_in[1];
    const float* value = (const float*)d_in[2];
    const int*   mask  = (const int*)d_in[3];
    const float* Wq    = (const float*)d_in[4];
    const float* Wk    = (const float*)d_in[5];
    const float* Wv    = (const float*)d_in[6];
    const float* Wo    = (const float*)d_in[7];
    const float* bo    = (const float*)d_in[8];
    float* out = (float*)d_out;

    float *Qp, *Kp, *Vp, *Op;
    uint32_t* MBp;
    cudaGetSymbolAddress((void**)&Qp, g_Q);
    cudaGetSymbolAddress((void**)&Kp, g_K);
    cudaGetSymbolAddress((void**)&Vp, g_V);
    cudaGetSymbolAddress((void**)&Op, g_O);
    cudaGetSymbolAddress((void**)&MBp, g_MB);

    dim3 blk(128);
    dim3 gproj(CE / 64, CL / 128);

    pack_mask<<<(CL * CS) / 256, 256>>>(mask, MBp);

    gemm_tc<<<gproj, blk>>>(query, Wq, nullptr, Qp, CL, CE, CE);
    gemm_tc<<<gproj, blk>>>(key,   Wk, nullptr, Kp, CS, CE, CE);
    gemm_tc<<<gproj, blk>>>(value, Wv, nullptr, Vp, CS, CE, CE);

    const int smem_bytes = (128 + 64 + 64 + 128) * FSTR * (int)sizeof(float); // 110592
    cudaFuncSetAttribute(flash_tc, cudaFuncAttributeMaxDynamicSharedMemorySize,
                         smem_bytes);
    flash_tc<<<dim3(CL / 128, CH), blk, smem_bytes>>>(Qp, Kp, Vp, MBp, Op);

    gemm_tc<<<gproj, blk>>>(Op, Wo, bo, out, CL, CE, CE);
}

// round 4
// speedup vs baseline: 4.0731x; 1.4899x over previous
#include <cuda_runtime.h>
#include <cstdint>

#define CL 4096
#define CS 4096
#define CE 768
#define CH 12
#define CD 64

#define QSTR 68   // Q/K row stride (words): row-step ≡ 4 mod 32 banks
#define VSTR 72   // V row stride (words): row-step ≡ 8 mod 32 banks
#define ASTR 36   // gemm A tile stride
#define WSTR 72   // gemm W tile stride

static __device__ __host__ constexpr float INV_SCALE = 0.036084391824351614f; // 1/sqrt(768)

__device__ float g_Q[CL * CE];
__device__ float g_K[CS * CE];
__device__ float g_V[CS * CE];
__device__ float g_O[CL * CE];
__device__ uint32_t g_MB[(size_t)CL * CS / 32];

// ---------------------------------------------------------------------------
__device__ __forceinline__ float to_tf32(float x) {
    uint32_t u;
    asm("cvt.rna.tf32.f32 %0, %1;" : "=r"(u) : "f"(x));
    return __uint_as_float(u);
}

__device__ __forceinline__ void mma_tf32(float c[4], float a0, float a1,
                                         float a2, float a3, float b0, float b1) {
    asm volatile(
        "mma.sync.aligned.m16n8k8.row.col.f32.tf32.tf32.f32 "
        "{%0,%1,%2,%3}, {%4,%5,%6,%7}, {%8,%9}, {%0,%1,%2,%3};\n"
        : "+f"(c[0]), "+f"(c[1]), "+f"(c[2]), "+f"(c[3])
        : "r"(__float_as_uint(a0)), "r"(__float_as_uint(a1)),
          "r"(__float_as_uint(a2)), "r"(__float_as_uint(a3)),
          "r"(__float_as_uint(b0)), "r"(__float_as_uint(b1)));
}

__device__ __forceinline__ uint32_t s2u(const void* p) {
    return (uint32_t)__cvta_generic_to_shared(p);
}
__device__ __forceinline__ void cpa(uint32_t d, const void* s) {
    asm volatile("cp.async.cg.shared.global [%0], [%1], 16;" :: "r"(d), "l"(s));
}
__device__ __forceinline__ void cpcommit() {
    asm volatile("cp.async.commit_group;");
}
template <int N> __device__ __forceinline__ void cpwait() {
    asm volatile("cp.async.wait_group %0;" :: "n"(N));
}

// ---------------------------------------------------------------------------
// Pack mask to bits, vectorized: bit i of word w = mask[w*32+i] != 0
// ---------------------------------------------------------------------------
__global__ __launch_bounds__(256) void pack_mask(const int* __restrict__ m,
                                                 uint32_t* __restrict__ mb) {
    __shared__ uint32_t nib[256];
    int t = threadIdx.x;
    size_t base = (size_t)blockIdx.x * 1024 + (size_t)t * 4;
    int4 v = *(const int4*)&m[base];
    nib[t] = (v.x ? 1u : 0u) | (v.y ? 2u : 0u) | (v.z ? 4u : 0u) | (v.w ? 8u : 0u);
    __syncthreads();
    if (t < 32) {
        uint32_t w = 0;
#pragma unroll
        for (int j = 0; j < 8; j++) w |= nib[t * 8 + j] << (4 * j);
        mb[(size_t)blockIdx.x * 32 + t] = w;
    }
}

// ---------------------------------------------------------------------------
// tf32 GEMM, cp.async double-buffered. C = (A@W)*scale (+bias) [round->tf32].
// Tile 128x64, 128 thr, warp tile 32x64, k-step 32.
// ---------------------------------------------------------------------------
__global__ __launch_bounds__(128) void gemm_tc(const float* __restrict__ A,
                                               const float* __restrict__ W,
                                               const float* __restrict__ bias,
                                               float* __restrict__ C,
                                               int M, int N, int K,
                                               float scale, int do_round)
{
    extern __shared__ float sg[];
    float* smA = sg;                       // 2 x 128 x ASTR
    float* smW = sg + 2 * 128 * ASTR;      // 2 x 32 x WSTR

    const int tid = threadIdx.x;
    const int wid = tid >> 5;
    const int ln  = tid & 31;
    const int gid = ln >> 2;
    const int tig = ln & 3;
    const int qb  = wid * 32;
    const int m0 = blockIdx.y * 128;
    const int n0 = blockIdx.x * 64;

    // async issue of one k-step tile into buffer b
    auto issue = [&](int k0, int b) {
        float* dA = smA + b * 128 * ASTR;
        float* dW = smW + b * 32 * WSTR;
#pragma unroll
        for (int i = 0; i < 8; i++) {
            int lin = tid + i * 128;
            int row = lin >> 3;
            int c4 = (lin & 7) << 2;
            cpa(s2u(&dA[row * ASTR + c4]), &A[(size_t)(m0 + row) * K + k0 + c4]);
        }
#pragma unroll
        for (int i = 0; i < 4; i++) {
            int lin = tid + i * 128;
            int kr = lin >> 4;
            int c4 = (lin & 15) << 2;
            cpa(s2u(&dW[kr * WSTR + c4]), &W[(size_t)(k0 + kr) * N + n0 + c4]);
        }
        cpcommit();
    };

    float c[2][8][4];
#pragma unroll
    for (int m = 0; m < 2; m++)
#pragma unroll
        for (int nf = 0; nf < 8; nf++)
#pragma unroll
            for (int j = 0; j < 4; j++) c[m][nf][j] = 0.f;

    const int NS = K / 32;  // 24
    issue(0, 0);
    issue(32, 1);

    for (int ks = 0; ks < NS; ks++) {
        const int buf = ks & 1;
        if (ks < NS - 1) cpwait<1>(); else cpwait<0>();
        __syncthreads();

        const float* Ab = smA + buf * 128 * ASTR;
        const float* Wb = smW + buf * 32 * WSTR;

#pragma unroll
        for (int kk = 0; kk < 4; kk++) {
            float a[2][4];
#pragma unroll
            for (int m = 0; m < 2; m++) {
                int base = (qb + m * 16 + gid) * ASTR + kk * 8 + tig;
                a[m][0] = to_tf32(Ab[base]);
                a[m][1] = to_tf32(Ab[base + 8 * ASTR]);
                a[m][2] = to_tf32(Ab[base + 4]);
                a[m][3] = to_tf32(Ab[base + 8 * ASTR + 4]);
            }
#pragma unroll
            for (int nf = 0; nf < 8; nf++) {
                float b0 = to_tf32(Wb[(kk * 8 + tig) * WSTR + nf * 8 + gid]);
                float b1 = to_tf32(Wb[(kk * 8 + tig + 4) * WSTR + nf * 8 + gid]);
#pragma unroll
                for (int m = 0; m < 2; m++)
                    mma_tf32(c[m][nf], a[m][0], a[m][1], a[m][2], a[m][3], b0, b1);
            }
        }
        __syncthreads();
        if (ks + 2 < NS) issue((ks + 2) * 32, buf);
    }

#pragma unroll
    for (int m = 0; m < 2; m++) {
        int r0 = m0 + qb + m * 16 + gid;
        int r1 = r0 + 8;
#pragma unroll
        for (int nf = 0; nf < 8; nf++) {
            int n = n0 + nf * 8 + 2 * tig;
            float v0 = c[m][nf][0] * scale, v1 = c[m][nf][1] * scale;
            float v2 = c[m][nf][2] * scale, v3 = c[m][nf][3] * scale;
            if (bias) { v0 += bias[n]; v1 += bias[n + 1]; v2 += bias[n]; v3 += bias[n + 1]; }
            if (do_round) {
                v0 = to_tf32(v0); v1 = to_tf32(v1);
                v2 = to_tf32(v2); v3 = to_tf32(v3);
            }
            *(float2*)&C[(size_t)r0 * N + n] = make_float2(v0, v1);
            *(float2*)&C[(size_t)r1 * N + n] = make_float2(v2, v3);
        }
    }
}

// ---------------------------------------------------------------------------
// Flash attention, cp.async double-buffered K/V, shuffle-based P redistribution.
// Block = (128 q, head), 4 warps x 32 rows. Q/K/V already tf32-rounded,
// Q already scaled by 1/sqrt(E).
// ---------------------------------------------------------------------------
__global__ __launch_bounds__(128) void flash_tc(const float* __restrict__ Qg,
                                                const float* __restrict__ Kg,
                                                const float* __restrict__ Vg,
                                                const uint32_t* __restrict__ MBg,
                                                float* __restrict__ Og)
{
    extern __shared__ float smx[];
    float* Qs = smx;                        // 128 x QSTR
    float* Ks = Qs + 128 * QSTR;            // 2 x 64 x QSTR
    float* Vs = Ks + 2 * 64 * QSTR;         // 2 x 64 x VSTR

    const uint2* MB2 = (const uint2*)MBg;

    const int h  = blockIdx.y;
    const int q0 = blockIdx.x * 128;
    const int tid = threadIdx.x;
    const int wid = tid >> 5;
    const int ln  = tid & 31;
    const int gid = ln >> 2;
    const int tig = ln & 3;
    const int qb = wid * 32;

    auto issueKV = [&](int k0, int b) {
        float* dK = Ks + b * 64 * QSTR;
        float* dV = Vs + b * 64 * VSTR;
#pragma unroll
        for (int i = 0; i < 8; i++) {
            int lin = tid + i * 128;
            int row = lin >> 4;
            int c4 = (lin & 15) << 2;
            cpa(s2u(&dK[row * QSTR + c4]), &Kg[(size_t)(k0 + row) * CE + h * CD + c4]);
            cpa(s2u(&dV[row * VSTR + c4]), &Vg[(size_t)(k0 + row) * CE + h * CD + c4]);
        }
        cpcommit();
    };

    // prologue: Q + tile0 (group 0), tile1 (group 1)
#pragma unroll
    for (int i = 0; i < 16; i++) {
        int lin = tid + i * 128;
        int row = lin >> 4;
        int c4 = (lin & 15) << 2;
        cpa(s2u(&Qs[row * QSTR + c4]), &Qg[(size_t)(q0 + row) * CE + h * CD + c4]);
    }
    {
        float* dK = Ks;
        float* dV = Vs;
#pragma unroll
        for (int i = 0; i < 8; i++) {
            int lin = tid + i * 128;
            int row = lin >> 4;
            int c4 = (lin & 15) << 2;
            cpa(s2u(&dK[row * QSTR + c4]), &Kg[(size_t)row * CE + h * CD + c4]);
            cpa(s2u(&dV[row * VSTR + c4]), &Vg[(size_t)row * CE + h * CD + c4]);
        }
        cpcommit();
    }
    issueKV(64, 1);

    float m_i[4] = {-1e30f, -1e30f, -1e30f, -1e30f};
    float l_i[4] = {0.f, 0.f, 0.f, 0.f};
    float o[2][8][4];
#pragma unroll
    for (int m = 0; m < 2; m++)
#pragma unroll
        for (int nf = 0; nf < 8; nf++)
#pragma unroll
            for (int j = 0; j < 4; j++) o[m][nf][j] = 0.f;

    const int mrow = q0 + qb + gid;
    const int NT = CS / 64;  // 64

    for (int t = 0; t < NT; t++) {
        const int buf = t & 1;
        if (t < NT - 1) cpwait<1>(); else cpwait<0>();
        __syncthreads();

        const float* Kb = Ks + buf * 64 * QSTR;
        const float* Vb = Vs + buf * 64 * VSTR;

        // mask bits for this tile
        uint2 mw[2][2];
#pragma unroll
        for (int m = 0; m < 2; m++) {
            mw[m][0] = MB2[(size_t)(mrow + m * 16) * 64 + t];
            mw[m][1] = MB2[(size_t)(mrow + m * 16 + 8) * 64 + t];
        }

        // S = Q @ K^T  (warp: 32 x 64)
        float s[2][8][4];
#pragma unroll
        for (int m = 0; m < 2; m++)
#pragma unroll
            for (int nf = 0; nf < 8; nf++)
#pragma unroll
                for (int j = 0; j < 4; j++) s[m][nf][j] = 0.f;

#pragma unroll
        for (int kk = 0; kk < 8; kk++) {
            float a[2][4];
#pragma unroll
            for (int m = 0; m < 2; m++) {
                int base = (qb + m * 16 + gid) * QSTR + kk * 8 + tig;
                a[m][0] = Qs[base];
                a[m][1] = Qs[base + 8 * QSTR];
                a[m][2] = Qs[base + 4];
                a[m][3] = Qs[base + 8 * QSTR + 4];
            }
#pragma unroll
            for (int nf = 0; nf < 8; nf++) {
                float b0 = Kb[(nf * 8 + gid) * QSTR + kk * 8 + tig];
                float b1 = Kb[(nf * 8 + gid) * QSTR + kk * 8 + tig + 4];
#pragma unroll
                for (int m = 0; m < 2; m++)
                    mma_tf32(s[m][nf], a[m][0], a[m][1], a[m][2], a[m][3], b0, b1);
            }
        }

        // online softmax + mask
#pragma unroll
        for (int m = 0; m < 2; m++) {
            float mx0 = -1e30f, mx1 = -1e30f;
#pragma unroll
            for (int nf = 0; nf < 8; nf++) {
                mx0 = fmaxf(mx0, fmaxf(s[m][nf][0], s[m][nf][1]));
                mx1 = fmaxf(mx1, fmaxf(s[m][nf][2], s[m][nf][3]));
            }
#pragma unroll
            for (int off = 1; off <= 2; off <<= 1) {
                mx0 = fmaxf(mx0, __shfl_xor_sync(0xffffffffu, mx0, off));
                mx1 = fmaxf(mx1, __shfl_xor_sync(0xffffffffu, mx1, off));
            }
            float mn0 = fmaxf(m_i[2 * m], mx0);
            float mn1 = fmaxf(m_i[2 * m + 1], mx1);
            float cr0 = __expf(m_i[2 * m] - mn0);
            float cr1 = __expf(m_i[2 * m + 1] - mn1);

            float sum0 = 0.f, sum1 = 0.f;
#pragma unroll
            for (int nf = 0; nf < 8; nf++) {
                uint32_t w0 = (nf < 4) ? mw[m][0].x : mw[m][0].y;
                uint32_t w1 = (nf < 4) ? mw[m][1].x : mw[m][1].y;
                int sh = ((nf & 3) << 3) + 2 * tig;
                float p0 = __expf(s[m][nf][0] - mn0);
                float p1 = __expf(s[m][nf][1] - mn0);
                float p2 = __expf(s[m][nf][2] - mn1);
                float p3 = __expf(s[m][nf][3] - mn1);
                p0 = ((w0 >> sh) & 1) ? p0 : 0.f;
                p1 = ((w0 >> (sh + 1)) & 1) ? p1 : 0.f;
                p2 = ((w1 >> sh) & 1) ? p2 : 0.f;
                p3 = ((w1 >> (sh + 1)) & 1) ? p3 : 0.f;
                s[m][nf][0] = p0; s[m][nf][1] = p1;
                s[m][nf][2] = p2; s[m][nf][3] = p3;
                sum0 += p0 + p1;
                sum1 += p2 + p3;
            }
#pragma unroll
            for (int off = 1; off <= 2; off <<= 1) {
                sum0 += __shfl_xor_sync(0xffffffffu, sum0, off);
                sum1 += __shfl_xor_sync(0xffffffffu, sum1, off);
            }
            l_i[2 * m]     = l_i[2 * m] * cr0 + sum0;
            l_i[2 * m + 1] = l_i[2 * m + 1] * cr1 + sum1;
            m_i[2 * m] = mn0;
            m_i[2 * m + 1] = mn1;
#pragma unroll
            for (int nf = 0; nf < 8; nf++) {
                o[m][nf][0] *= cr0; o[m][nf][1] *= cr0;
                o[m][nf][2] *= cr1; o[m][nf][3] *= cr1;
            }
        }

        // O += P @ V : A-frags built from S C-frags via lane shuffles
        const int srcA = 4 * gid + (tig >> 1);
        const int srcB = srcA + 2;
        const bool odd = (tig & 1);
#pragma unroll
        for (int g = 0; g < 8; g++) {
            float a[2][4];
#pragma unroll
            for (int m = 0; m < 2; m++) {
                float x0 = __shfl_sync(0xffffffffu, s[m][g][0], srcA);
                float x1 = __shfl_sync(0xffffffffu, s[m][g][1], srcA);
                float y0 = __shfl_sync(0xffffffffu, s[m][g][2], srcA);
                float y1 = __shfl_sync(0xffffffffu, s[m][g][3], srcA);
                float x2 = __shfl_sync(0xffffffffu, s[m][g][0], srcB);
                float x3 = __shfl_sync(0xffffffffu, s[m][g][1], srcB);
                float y2 = __shfl_sync(0xffffffffu, s[m][g][2], srcB);
                float y3 = __shfl_sync(0xffffffffu, s[m][g][3], srcB);
                a[m][0] = to_tf32(odd ? x1 : x0);
                a[m][1] = to_tf32(odd ? y1 : y0);
                a[m][2] = to_tf32(odd ? x3 : x2);
                a[m][3] = to_tf32(odd ? y3 : y2);
            }
#pragma unroll
            for (int nf = 0; nf < 8; nf++) {
                float b0 = Vb[(g * 8 + tig) * VSTR + nf * 8 + gid];
                float b1 = Vb[(g * 8 + tig + 4) * VSTR + nf * 8 + gid];
#pragma unroll
                for (int m = 0; m < 2; m++)
                    mma_tf32(o[m][nf], a[m][0], a[m][1], a[m][2], a[m][3], b0, b1);
            }
        }

        __syncthreads();
        if (t + 2 < NT) issueKV((t + 2) * 64, buf);
    }

    // epilogue
#pragma unroll
    for (int m = 0; m < 2; m++) {
        float inv0 = (l_i[2 * m] > 0.f) ? (1.f / l_i[2 * m]) : 0.f;
        float inv1 = (l_i[2 * m + 1] > 0.f) ? (1.f / l_i[2 * m + 1]) : 0.f;
        int r0 = q0 + qb + m * 16 + gid;
#pragma unroll
        for (int nf = 0; nf < 8; nf++) {
            int cc = h * CD + nf * 8 + 2 * tig;
            *(float2*)&Og[(size_t)r0 * CE + cc] =
                make_float2(o[m][nf][0] * inv0, o[m][nf][1] * inv0);
            *(float2*)&Og[(size_t)(r0 + 8) * CE + cc] =
                make_float2(o[m][nf][2] * inv1, o[m][nf][3] * inv1);
        }
    }
}

// ---------------------------------------------------------------------------

extern "C" void kernel_launch(void* const* d_in, const int* in_sizes, int n_in,
                              void* d_out, int out_size)
{
    const float* query = (const float*)d_in[0];
    const float* key   = (const float*)d_in[1];
    const float* value = (const float*)d_in[2];
    const int*   mask  = (const int*)d_in[3];
    const float* Wq    = (const float*)d_in[4];
    const float* Wk    = (const float*)d_in[5];
    const float* Wv    = (const float*)d_in[6];
    const float* Wo    = (const float*)d_in[7];
    const float* bo    = (const float*)d_in[8];
    float* out = (float*)d_out;

    float *Qp, *Kp, *Vp, *Op;
    uint32_t* MBp;
    cudaGetSymbolAddress((void**)&Qp, g_Q);
    cudaGetSymbolAddress((void**)&Kp, g_K);
    cudaGetSymbolAddress((void**)&Vp, g_V);
    cudaGetSymbolAddress((void**)&Op, g_O);
    cudaGetSymbolAddress((void**)&MBp, g_MB);

    const int gemm_smem = (2 * 128 * ASTR + 2 * 32 * WSTR) * (int)sizeof(float);   // 55296
    const int flash_smem = (128 * QSTR + 2 * 64 * QSTR + 2 * 64 * VSTR) * (int)sizeof(float); // 106496

    cudaFuncSetAttribute(gemm_tc, cudaFuncAttributeMaxDynamicSharedMemorySize, gemm_smem);
    cudaFuncSetAttribute(flash_tc, cudaFuncAttributeMaxDynamicSharedMemorySize, flash_smem);

    dim3 blk(128);
    dim3 gproj(CE / 64, CL / 128);

    pack_mask<<<(CL * CS) / 1024, 256>>>(mask, MBp);

    gemm_tc<<<gproj, blk, gemm_smem>>>(query, Wq, nullptr, Qp, CL, CE, CE, INV_SCALE, 1);
    gemm_tc<<<gproj, blk, gemm_smem>>>(key,   Wk, nullptr, Kp, CS, CE, CE, 1.0f, 1);
    gemm_tc<<<gproj, blk, gemm_smem>>>(value, Wv, nullptr, Vp, CS, CE, CE, 1.0f, 1);

    flash_tc<<<dim3(CL / 128, CH), blk, flash_smem>>>(Qp, Kp, Vp, MBp, Op);

    gemm_tc<<<gproj, blk, gemm_smem>>>(Op, Wo, bo, out, CL, CE, CE, 1.0f, 0);
}